// round 15
// baseline (speedup 1.0000x reference)
#include <cuda_runtime.h>
#include <cuda_fp16.h>
#include <cstdint>

// ---------------------------------------------------------------------------
// CausalSelfAttention: B=4, S=2048, D=1024, fp32, causal softmax (scale 1/32)
// Pipeline: [cvt inputs->fp16] -> [proj Q,K,Vt] -> [scores lower-tri] ->
//           [softmax -> fp16 P] -> [PV -> out]
// fp16 mma.sync m16n8k16 (f32 accum), k-major operands, V transposed.
// 128x128 CTA tile, BK=64, 2-stage cp.async, 4 warps @ 64x64.
// Register double-buffered fragments (LDS of ks+1 overlaps HMMA of ks).
// ---------------------------------------------------------------------------

#define BATCH 4
#define SEQ   2048
#define DIM   1024
#define NQT   (SEQ / 128)
#define NTRI  (NQT * (NQT + 1) / 2)   // 136 lower-tri tiles

__device__ __align__(256) __half g_Xh [(size_t)BATCH * SEQ * DIM];
__device__ __align__(256) __half g_Wqh[(size_t)DIM * DIM];
__device__ __align__(256) __half g_Wkh[(size_t)DIM * DIM];
__device__ __align__(256) __half g_Wvh[(size_t)DIM * DIM];
__device__ __align__(256) __half g_Qh [(size_t)BATCH * SEQ * DIM];
__device__ __align__(256) __half g_Kh [(size_t)BATCH * SEQ * DIM];
__device__ __align__(256) __half g_Vth[(size_t)BATCH * DIM * SEQ]; // [b][e][k]
__device__ __align__(256) float  g_S  [(size_t)BATCH * SEQ * SEQ];
__device__ __align__(256) __half g_Ph [(size_t)BATCH * SEQ * SEQ];

// ---------------------------------------------------------------------------
__device__ __forceinline__ void mma_f16(float* d, const uint32_t* a,
                                        const uint32_t* b, const float* c) {
    asm volatile(
        "mma.sync.aligned.m16n8k16.row.col.f32.f16.f16.f32 "
        "{%0,%1,%2,%3}, {%4,%5,%6,%7}, {%8,%9}, {%10,%11,%12,%13};\n"
        : "=f"(d[0]), "=f"(d[1]), "=f"(d[2]), "=f"(d[3])
        : "r"(a[0]), "r"(a[1]), "r"(a[2]), "r"(a[3]),
          "r"(b[0]), "r"(b[1]),
          "f"(c[0]), "f"(c[1]), "f"(c[2]), "f"(c[3]));
}

__device__ __forceinline__ void cpa16(void* smem, const void* g) {
    uint32_t s = (uint32_t)__cvta_generic_to_shared(smem);
    asm volatile("cp.async.cg.shared.global [%0], [%1], 16;\n" :: "r"(s), "l"(g));
}
#define CP_COMMIT() asm volatile("cp.async.commit_group;\n")
#define CP_WAIT(n)  asm volatile("cp.async.wait_group %0;\n" :: "n"(n))

// ---------------------------------------------------------------------------
// fp16 GEMM core: C[128x128] tile = A[128,K] @ B[128,K]^T, both k-major.
// BK=64 halves, 2-stage double buffer, 128 threads, warp 64x64.
// Register-level fragment double-buffering across the 4 K=16 sub-steps.
// EPI 0: fp32 -> Cf.  EPI 1: fp16 -> Ch.  EPI 2: fp16 transposed -> Ch.
// ---------------------------------------------------------------------------
template <int EPI>
__device__ __forceinline__ void gemm_fp16(const __half* __restrict__ A,
                                          const __half* __restrict__ B,
                                          float* __restrict__ Cf,
                                          __half* __restrict__ Ch,
                                          int lda, int ldb, int ldc,
                                          int kIters, int row0, int col0,
                                          int row0c) {
    constexpr int BM = 128, BK = 64, STR = 72;   // halves; 144B rows

    extern __shared__ __half smh[];
    __half* As = smh;                            // [2][128][72]
    __half* Bs = smh + (size_t)2 * BM * STR;     // [2][128][72]

    const int tid  = threadIdx.x;     // 0..127
    const int warp = tid >> 5;        // 0..3
    const int lane = tid & 31;
    const int wm   = (warp >> 1) * 64;
    const int wn   = (warp & 1) * 64;
    const int gid  = lane >> 2;       // 0..7
    const int tig  = lane & 3;        // 0..3

    float acc[4][8][4];
#pragma unroll
    for (int i = 0; i < 4; i++)
#pragma unroll
        for (int j = 0; j < 8; j++)
#pragma unroll
            for (int r = 0; r < 4; r++) acc[i][j][r] = 0.f;

    auto loadA = [&](int kt, int buf) {
#pragma unroll
        for (int i = 0; i < 8; i++) {            // 128 rows x 8 16B-chunks
            int f = tid + i * 128;
            int r = f >> 3, q = f & 7;
            cpa16(&As[((size_t)(buf * BM + r)) * STR + q * 8],
                  &A[(size_t)(row0 + r) * lda + kt * BK + q * 8]);
        }
    };
    auto loadB = [&](int kt, int buf) {
#pragma unroll
        for (int i = 0; i < 8; i++) {
            int f = tid + i * 128;
            int r = f >> 3, q = f & 7;
            cpa16(&Bs[((size_t)(buf * BM + r)) * STR + q * 8],
                  &B[(size_t)(col0 + r) * ldb + kt * BK + q * 8]);
        }
    };

    // fragment loader for K=16 sub-step ks out of smem buffer buf
    auto loadFrag = [&](int ks, int buf, uint32_t af[4][4], uint32_t bf[8][2]) {
        const int kk = ks * 16;
#pragma unroll
        for (int mf = 0; mf < 4; mf++) {
            const __half* a0 = &As[((size_t)(buf * BM + wm + mf * 16 + gid)) * STR + kk + 2 * tig];
            const __half* a1 = a0 + 8 * STR;
            af[mf][0] = *(const uint32_t*)a0;
            af[mf][1] = *(const uint32_t*)a1;
            af[mf][2] = *(const uint32_t*)(a0 + 8);
            af[mf][3] = *(const uint32_t*)(a1 + 8);
        }
#pragma unroll
        for (int nf = 0; nf < 8; nf++) {
            const __half* b0 = &Bs[((size_t)(buf * BM + wn + nf * 8 + gid)) * STR + kk + 2 * tig];
            bf[nf][0] = *(const uint32_t*)b0;
            bf[nf][1] = *(const uint32_t*)(b0 + 8);
        }
    };

    loadA(0, 0);
    loadB(0, 0);
    CP_COMMIT();

    uint32_t af[2][4][4];
    uint32_t bf[2][8][2];

    int buf = 0;
    for (int kt = 0; kt < kIters; kt++) {
        if (kt + 1 < kIters) {
            loadA(kt + 1, buf ^ 1);
            loadB(kt + 1, buf ^ 1);
            CP_COMMIT();
            CP_WAIT(1);
        } else {
            CP_WAIT(0);
        }
        __syncthreads();

        loadFrag(0, buf, af[0], bf[0]);
#pragma unroll
        for (int ks = 0; ks < 4; ks++) {
            const int cur = ks & 1;
            if (ks < 3) loadFrag(ks + 1, buf, af[cur ^ 1], bf[cur ^ 1]);
#pragma unroll
            for (int mf = 0; mf < 4; mf++)
#pragma unroll
                for (int nf = 0; nf < 8; nf++)
                    mma_f16(acc[mf][nf], af[cur][mf], bf[cur][nf], acc[mf][nf]);
        }
        __syncthreads();
        buf ^= 1;
    }

#pragma unroll
    for (int mf = 0; mf < 4; mf++) {
#pragma unroll
        for (int nf = 0; nf < 8; nf++) {
            int r = row0c + wm + mf * 16 + gid;
            int c = col0 + wn + nf * 8 + tig * 2;
            float v0 = acc[mf][nf][0], v1 = acc[mf][nf][1];
            float v2 = acc[mf][nf][2], v3 = acc[mf][nf][3];
            if (EPI == 0) {
                Cf[(size_t)r * ldc + c]           = v0;
                Cf[(size_t)r * ldc + c + 1]       = v1;
                Cf[(size_t)(r + 8) * ldc + c]     = v2;
                Cf[(size_t)(r + 8) * ldc + c + 1] = v3;
            } else if (EPI == 1) {
                *(__half2*)&Ch[(size_t)r * ldc + c]       = __floats2half2_rn(v0, v1);
                *(__half2*)&Ch[(size_t)(r + 8) * ldc + c] = __floats2half2_rn(v2, v3);
            } else {  // transposed: Ch[e][k] = C[k][e]
                Ch[(size_t)c * ldc + r]           = __float2half(v0);
                Ch[(size_t)(c + 1) * ldc + r]     = __float2half(v1);
                Ch[(size_t)c * ldc + r + 8]       = __float2half(v2);
                Ch[(size_t)(c + 1) * ldc + r + 8] = __float2half(v3);
            }
        }
    }
}

#define SMEM_GEMM (4 * 128 * 72 * 2)   // 73728 bytes

// ---------------------------------------------------------------------------
// kernels
// ---------------------------------------------------------------------------
__global__ __launch_bounds__(256) void cvt_kernel(const float4* __restrict__ x,
                                                  const float4* __restrict__ wq,
                                                  const float4* __restrict__ wk,
                                                  const float4* __restrict__ wv) {
    const float4* src;
    __half2* dst;
    int n4;
    switch (blockIdx.y) {
        case 0: src = x;  dst = (__half2*)g_Xh;  n4 = BATCH * SEQ * DIM / 4; break;
        case 1: src = wq; dst = (__half2*)g_Wqh; n4 = DIM * DIM / 4; break;
        case 2: src = wk; dst = (__half2*)g_Wkh; n4 = DIM * DIM / 4; break;
        default: src = wv; dst = (__half2*)g_Wvh; n4 = DIM * DIM / 4; break;
    }
    for (int i = blockIdx.x * 256 + threadIdx.x; i < n4; i += gridDim.x * 256) {
        float4 v = src[i];
        dst[i * 2]     = __floats2half2_rn(v.x, v.y);
        dst[i * 2 + 1] = __floats2half2_rn(v.z, v.w);
    }
}

__global__ __launch_bounds__(128) void proj_kernel() {
    const int z = blockIdx.z;
    const int row0 = blockIdx.y * 128;
    const int col0 = blockIdx.x * 128;
    if (z == 0) {
        gemm_fp16<1>(g_Xh, g_Wqh, nullptr, g_Qh, DIM, DIM, DIM, 16,
                     row0, col0, row0);
    } else if (z == 1) {
        gemm_fp16<1>(g_Xh, g_Wkh, nullptr, g_Kh, DIM, DIM, DIM, 16,
                     row0, col0, row0);
    } else {  // V: store transposed per batch -> g_Vth[b][e][k]
        const int b = row0 / SEQ;
        gemm_fp16<2>(g_Xh, g_Wvh, nullptr, g_Vth + (size_t)b * DIM * SEQ,
                     DIM, DIM, SEQ, 16, row0, col0, row0 % SEQ);
    }
}

__device__ __forceinline__ void tri_decode(int t, int& qt, int& kt) {
    int q = (int)((sqrtf(8.0f * t + 1.0f) - 1.0f) * 0.5f);
    while ((q + 1) * (q + 2) / 2 <= t) q++;
    while (q * (q + 1) / 2 > t) q--;
    qt = q;
    kt = t - q * (q + 1) / 2;
}

__global__ __launch_bounds__(128) void scores_kernel() {
    int qt, kt;
    tri_decode(blockIdx.x, qt, kt);
    int b = blockIdx.z;
    gemm_fp16<0>(g_Qh + (size_t)b * SEQ * DIM, g_Kh + (size_t)b * SEQ * DIM,
                 g_S + (size_t)b * SEQ * SEQ, nullptr,
                 DIM, DIM, SEQ, 16, qt * 128, kt * 128, qt * 128);
}

__global__ __launch_bounds__(256) void softmax_kernel() {
    const int row = blockIdx.x;
    const int b = row / SEQ, q = row % SEQ;
    const float* p = g_S + (size_t)b * SEQ * SEQ + (size_t)q * SEQ;
    __half* ph = g_Ph + (size_t)b * SEQ * SEQ + (size_t)q * SEQ;
    const int len  = q + 1;
    const int kend = ((q / 128) + 1) * 128;   // PV reads k < (qt+1)*128
    const float scale = 0.03125f;             // 1/sqrt(1024)

    __shared__ float red[8];
    __shared__ float red2[8];

    float vals[8];
    int cnt = 0;
    float m = -1e30f;
    for (int i = threadIdx.x; i < len; i += 256) {
        float v = p[i];
        vals[cnt++] = v;
        m = fmaxf(m, v);
    }
#pragma unroll
    for (int o = 16; o; o >>= 1) m = fmaxf(m, __shfl_xor_sync(~0u, m, o));
    if ((threadIdx.x & 31) == 0) red[threadIdx.x >> 5] = m;
    __syncthreads();
    m = red[0];
#pragma unroll
    for (int i = 1; i < 8; i++) m = fmaxf(m, red[i]);

    float s = 0.f;
#pragma unroll 8
    for (int j = 0; j < cnt; j++) {
        float e = __expf(scale * (vals[j] - m));
        vals[j] = e;
        s += e;
    }
#pragma unroll
    for (int o = 16; o; o >>= 1) s += __shfl_xor_sync(~0u, s, o);
    if ((threadIdx.x & 31) == 0) red2[threadIdx.x >> 5] = s;
    __syncthreads();
    s = 0.f;
#pragma unroll
    for (int i = 0; i < 8; i++) s += red2[i];
    const float inv = 1.0f / s;

    cnt = 0;
    for (int i = threadIdx.x; i < len; i += 256)
        ph[i] = __float2half(vals[cnt++] * inv);
    for (int i = len + threadIdx.x; i < kend; i += 256)
        ph[i] = __float2half(0.f);
}

__global__ __launch_bounds__(128) void pv_kernel(float* __restrict__ out) {
    int qt = blockIdx.y, et = blockIdx.x, b = blockIdx.z;
    // causal: k range = (qt+1)*128 => kIters = (qt+1)*2 at BK=64
    gemm_fp16<0>(g_Ph + (size_t)b * SEQ * SEQ, g_Vth + (size_t)b * DIM * SEQ,
                 out + (size_t)b * SEQ * DIM, nullptr,
                 SEQ, SEQ, DIM, (qt + 1) * 2, qt * 128, et * 128, qt * 128);
}

// ---------------------------------------------------------------------------
extern "C" void kernel_launch(void* const* d_in, const int* in_sizes, int n_in,
                              void* d_out, int out_size) {
    int xi = 0;
    for (int i = 0; i < n_in; i++)
        if (in_sizes[i] == BATCH * SEQ * DIM) { xi = i; break; }
    const float* x = (const float*)d_in[xi];
    const float* w[3];
    int wi = 0;
    for (int i = 0; i < n_in && wi < 3; i++)
        if (i != xi) w[wi++] = (const float*)d_in[i];
    float* out = (float*)d_out;

    cudaFuncSetAttribute(proj_kernel,
                         cudaFuncAttributeMaxDynamicSharedMemorySize, SMEM_GEMM);
    cudaFuncSetAttribute(scores_kernel,
                         cudaFuncAttributeMaxDynamicSharedMemorySize, SMEM_GEMM);
    cudaFuncSetAttribute(pv_kernel,
                         cudaFuncAttributeMaxDynamicSharedMemorySize, SMEM_GEMM);

    cvt_kernel<<<dim3(512, 4), 256>>>((const float4*)x, (const float4*)w[0],
                                      (const float4*)w[1], (const float4*)w[2]);
    proj_kernel<<<dim3(8, 64, 3), 128, SMEM_GEMM>>>();
    scores_kernel<<<dim3(NTRI, 1, 4), 128, SMEM_GEMM>>>();
    softmax_kernel<<<BATCH * SEQ, 256>>>();
    pv_kernel<<<dim3(8, 16, 4), 128, SMEM_GEMM>>>(out);
}

// round 17
// speedup vs baseline: 1.0276x; 1.0276x over previous
#include <cuda_runtime.h>
#include <cuda_fp16.h>
#include <cstdint>

// ---------------------------------------------------------------------------
// CausalSelfAttention: B=4, S=2048, D=1024, fp32, causal softmax (scale 1/32)
// Pipeline: [cvt inputs->fp16] -> [proj Q,K,Vt] -> [scores lower-tri] ->
//           [softmax -> fp16 P] -> [PV -> out]
// fp16 mma.sync m16n8k16 (f32 accum), k-major operands, V transposed.
// 128x128 CTA tile, BK=64, 2-stage cp.async, 4 warps @ 64x64.  (r12 base)
// NEW: pv launches big q-tiles first (LPT); softmax float4-vectorized+masked.
// ---------------------------------------------------------------------------

#define BATCH 4
#define SEQ   2048
#define DIM   1024
#define NQT   (SEQ / 128)
#define NTRI  (NQT * (NQT + 1) / 2)   // 136 lower-tri tiles

__device__ __align__(256) __half g_Xh [(size_t)BATCH * SEQ * DIM];
__device__ __align__(256) __half g_Wqh[(size_t)DIM * DIM];
__device__ __align__(256) __half g_Wkh[(size_t)DIM * DIM];
__device__ __align__(256) __half g_Wvh[(size_t)DIM * DIM];
__device__ __align__(256) __half g_Qh [(size_t)BATCH * SEQ * DIM];
__device__ __align__(256) __half g_Kh [(size_t)BATCH * SEQ * DIM];
__device__ __align__(256) __half g_Vth[(size_t)BATCH * DIM * SEQ]; // [b][e][k]
__device__ __align__(256) float  g_S  [(size_t)BATCH * SEQ * SEQ];
__device__ __align__(256) __half g_Ph [(size_t)BATCH * SEQ * SEQ];

// ---------------------------------------------------------------------------
__device__ __forceinline__ void mma_f16(float* d, const uint32_t* a,
                                        const uint32_t* b, const float* c) {
    asm volatile(
        "mma.sync.aligned.m16n8k16.row.col.f32.f16.f16.f32 "
        "{%0,%1,%2,%3}, {%4,%5,%6,%7}, {%8,%9}, {%10,%11,%12,%13};\n"
        : "=f"(d[0]), "=f"(d[1]), "=f"(d[2]), "=f"(d[3])
        : "r"(a[0]), "r"(a[1]), "r"(a[2]), "r"(a[3]),
          "r"(b[0]), "r"(b[1]),
          "f"(c[0]), "f"(c[1]), "f"(c[2]), "f"(c[3]));
}

__device__ __forceinline__ void cpa16(void* smem, const void* g) {
    uint32_t s = (uint32_t)__cvta_generic_to_shared(smem);
    asm volatile("cp.async.cg.shared.global [%0], [%1], 16;\n" :: "r"(s), "l"(g));
}
#define CP_COMMIT() asm volatile("cp.async.commit_group;\n")
#define CP_WAIT(n)  asm volatile("cp.async.wait_group %0;\n" :: "n"(n))

// ---------------------------------------------------------------------------
// fp16 GEMM core: C[128x128] tile = A[128,K] @ B[128,K]^T, both k-major.
// BK=64 halves, 2-stage double buffer, 128 threads, warp 64x64.
// EPI 0: fp32 -> Cf.  EPI 1: fp16 -> Ch.  EPI 2: fp16 transposed -> Ch.
// ---------------------------------------------------------------------------
template <int EPI>
__device__ __forceinline__ void gemm_fp16(const __half* __restrict__ A,
                                          const __half* __restrict__ B,
                                          float* __restrict__ Cf,
                                          __half* __restrict__ Ch,
                                          int lda, int ldb, int ldc,
                                          int kIters, int row0, int col0,
                                          int row0c) {
    constexpr int BM = 128, BK = 64, STR = 72;   // halves; 144B rows

    extern __shared__ __half smh[];
    __half* As = smh;                            // [2][128][72]
    __half* Bs = smh + (size_t)2 * BM * STR;     // [2][128][72]

    const int tid  = threadIdx.x;     // 0..127
    const int warp = tid >> 5;        // 0..3
    const int lane = tid & 31;
    const int wm   = (warp >> 1) * 64;
    const int wn   = (warp & 1) * 64;
    const int gid  = lane >> 2;       // 0..7
    const int tig  = lane & 3;        // 0..3

    float acc[4][8][4];
#pragma unroll
    for (int i = 0; i < 4; i++)
#pragma unroll
        for (int j = 0; j < 8; j++)
#pragma unroll
            for (int r = 0; r < 4; r++) acc[i][j][r] = 0.f;

    auto loadA = [&](int kt, int buf) {
#pragma unroll
        for (int i = 0; i < 8; i++) {            // 128 rows x 8 16B-chunks
            int f = tid + i * 128;
            int r = f >> 3, q = f & 7;
            cpa16(&As[((size_t)(buf * BM + r)) * STR + q * 8],
                  &A[(size_t)(row0 + r) * lda + kt * BK + q * 8]);
        }
    };
    auto loadB = [&](int kt, int buf) {
#pragma unroll
        for (int i = 0; i < 8; i++) {
            int f = tid + i * 128;
            int r = f >> 3, q = f & 7;
            cpa16(&Bs[((size_t)(buf * BM + r)) * STR + q * 8],
                  &B[(size_t)(col0 + r) * ldb + kt * BK + q * 8]);
        }
    };

    loadA(0, 0);
    loadB(0, 0);
    CP_COMMIT();

    int buf = 0;
    for (int kt = 0; kt < kIters; kt++) {
        if (kt + 1 < kIters) {
            loadA(kt + 1, buf ^ 1);
            loadB(kt + 1, buf ^ 1);
            CP_COMMIT();
            CP_WAIT(1);
        } else {
            CP_WAIT(0);
        }
        __syncthreads();

#pragma unroll
        for (int ks = 0; ks < 4; ks++) {         // 4 x K=16 per 64-k tile
            const int kk = ks * 16;
            uint32_t af[4][4];
#pragma unroll
            for (int mf = 0; mf < 4; mf++) {
                const __half* a0 = &As[((size_t)(buf * BM + wm + mf * 16 + gid)) * STR + kk + 2 * tig];
                const __half* a1 = a0 + 8 * STR;  // row +8
                af[mf][0] = *(const uint32_t*)a0;
                af[mf][1] = *(const uint32_t*)a1;
                af[mf][2] = *(const uint32_t*)(a0 + 8);
                af[mf][3] = *(const uint32_t*)(a1 + 8);
            }
            uint32_t bf[8][2];
#pragma unroll
            for (int nf = 0; nf < 8; nf++) {
                const __half* b0 = &Bs[((size_t)(buf * BM + wn + nf * 8 + gid)) * STR + kk + 2 * tig];
                bf[nf][0] = *(const uint32_t*)b0;
                bf[nf][1] = *(const uint32_t*)(b0 + 8);
            }
#pragma unroll
            for (int mf = 0; mf < 4; mf++)
#pragma unroll
                for (int nf = 0; nf < 8; nf++)
                    mma_f16(acc[mf][nf], af[mf], bf[nf], acc[mf][nf]);
        }
        __syncthreads();
        buf ^= 1;
    }

#pragma unroll
    for (int mf = 0; mf < 4; mf++) {
#pragma unroll
        for (int nf = 0; nf < 8; nf++) {
            int r = row0c + wm + mf * 16 + gid;
            int c = col0 + wn + nf * 8 + tig * 2;
            float v0 = acc[mf][nf][0], v1 = acc[mf][nf][1];
            float v2 = acc[mf][nf][2], v3 = acc[mf][nf][3];
            if (EPI == 0) {
                Cf[(size_t)r * ldc + c]           = v0;
                Cf[(size_t)r * ldc + c + 1]       = v1;
                Cf[(size_t)(r + 8) * ldc + c]     = v2;
                Cf[(size_t)(r + 8) * ldc + c + 1] = v3;
            } else if (EPI == 1) {
                *(__half2*)&Ch[(size_t)r * ldc + c]       = __floats2half2_rn(v0, v1);
                *(__half2*)&Ch[(size_t)(r + 8) * ldc + c] = __floats2half2_rn(v2, v3);
            } else {  // transposed: Ch[e][k] = C[k][e]
                Ch[(size_t)c * ldc + r]           = __float2half(v0);
                Ch[(size_t)(c + 1) * ldc + r]     = __float2half(v1);
                Ch[(size_t)c * ldc + r + 8]       = __float2half(v2);
                Ch[(size_t)(c + 1) * ldc + r + 8] = __float2half(v3);
            }
        }
    }
}

#define SMEM_GEMM (4 * 128 * 72 * 2)   // 73728 bytes

// ---------------------------------------------------------------------------
// kernels
// ---------------------------------------------------------------------------
__global__ __launch_bounds__(256) void cvt_kernel(const float4* __restrict__ x,
                                                  const float4* __restrict__ wq,
                                                  const float4* __restrict__ wk,
                                                  const float4* __restrict__ wv) {
    const float4* src;
    __half2* dst;
    int n4;
    switch (blockIdx.y) {
        case 0: src = x;  dst = (__half2*)g_Xh;  n4 = BATCH * SEQ * DIM / 4; break;
        case 1: src = wq; dst = (__half2*)g_Wqh; n4 = DIM * DIM / 4; break;
        case 2: src = wk; dst = (__half2*)g_Wkh; n4 = DIM * DIM / 4; break;
        default: src = wv; dst = (__half2*)g_Wvh; n4 = DIM * DIM / 4; break;
    }
    for (int i = blockIdx.x * 256 + threadIdx.x; i < n4; i += gridDim.x * 256) {
        float4 v = src[i];
        dst[i * 2]     = __floats2half2_rn(v.x, v.y);
        dst[i * 2 + 1] = __floats2half2_rn(v.z, v.w);
    }
}

__global__ __launch_bounds__(128) void proj_kernel() {
    const int z = blockIdx.z;
    const int row0 = blockIdx.y * 128;
    const int col0 = blockIdx.x * 128;
    if (z == 0) {
        gemm_fp16<1>(g_Xh, g_Wqh, nullptr, g_Qh, DIM, DIM, DIM, 16,
                     row0, col0, row0);
    } else if (z == 1) {
        gemm_fp16<1>(g_Xh, g_Wkh, nullptr, g_Kh, DIM, DIM, DIM, 16,
                     row0, col0, row0);
    } else {  // V: store transposed per batch -> g_Vth[b][e][k]
        const int b = row0 / SEQ;
        gemm_fp16<2>(g_Xh, g_Wvh, nullptr, g_Vth + (size_t)b * DIM * SEQ,
                     DIM, DIM, SEQ, 16, row0, col0, row0 % SEQ);
    }
}

__device__ __forceinline__ void tri_decode(int t, int& qt, int& kt) {
    int q = (int)((sqrtf(8.0f * t + 1.0f) - 1.0f) * 0.5f);
    while ((q + 1) * (q + 2) / 2 <= t) q++;
    while (q * (q + 1) / 2 > t) q--;
    qt = q;
    kt = t - q * (q + 1) / 2;
}

__global__ __launch_bounds__(128) void scores_kernel() {
    int qt, kt;
    tri_decode(blockIdx.x, qt, kt);
    int b = blockIdx.z;
    gemm_fp16<0>(g_Qh + (size_t)b * SEQ * DIM, g_Kh + (size_t)b * SEQ * DIM,
                 g_S + (size_t)b * SEQ * SEQ, nullptr,
                 DIM, DIM, SEQ, 16, qt * 128, kt * 128, qt * 128);
}

// Vectorized masked softmax: each thread owns up to 2 float4 chunks of the
// kend-padded row. Masked lanes (j > q) read as -1e30 -> exp = 0, which also
// produces the zero-fill PV needs in [len, kend).
__global__ __launch_bounds__(256) void softmax_kernel() {
    const int row = blockIdx.x;
    const int b = row / SEQ, q = row % SEQ;
    const float4* p4 = (const float4*)(g_S + (size_t)b * SEQ * SEQ + (size_t)q * SEQ);
    __half* ph = g_Ph + (size_t)b * SEQ * SEQ + (size_t)q * SEQ;
    const int kend = ((q >> 7) + 1) << 7;     // multiple of 128
    const float scale = 0.03125f;             // 1/sqrt(1024)
    const int tid = threadIdx.x;

    __shared__ float red[8];
    __shared__ float red2[8];

    float v[2][4];
    float m = -1e30f;
#pragma unroll
    for (int c = 0; c < 2; c++) {
        const int j0 = c * 1024 + tid * 4;
        if (j0 < kend) {
            float4 t = p4[c * 256 + tid];
            v[c][0] = (j0     <= q) ? t.x : -1e30f;
            v[c][1] = (j0 + 1 <= q) ? t.y : -1e30f;
            v[c][2] = (j0 + 2 <= q) ? t.z : -1e30f;
            v[c][3] = (j0 + 3 <= q) ? t.w : -1e30f;
            m = fmaxf(m, fmaxf(fmaxf(v[c][0], v[c][1]), fmaxf(v[c][2], v[c][3])));
        } else {
            v[c][0] = v[c][1] = v[c][2] = v[c][3] = -1e30f;
        }
    }
#pragma unroll
    for (int o = 16; o; o >>= 1) m = fmaxf(m, __shfl_xor_sync(~0u, m, o));
    if ((tid & 31) == 0) red[tid >> 5] = m;
    __syncthreads();
    m = red[0];
#pragma unroll
    for (int i = 1; i < 8; i++) m = fmaxf(m, red[i]);

    float s = 0.f;
#pragma unroll
    for (int c = 0; c < 2; c++)
#pragma unroll
        for (int j = 0; j < 4; j++) {
            float e = __expf(scale * (v[c][j] - m));   // masked -> 0
            v[c][j] = e;
            s += e;
        }
#pragma unroll
    for (int o = 16; o; o >>= 1) s += __shfl_xor_sync(~0u, s, o);
    if ((tid & 31) == 0) red2[tid >> 5] = s;
    __syncthreads();
    s = 0.f;
#pragma unroll
    for (int i = 0; i < 8; i++) s += red2[i];
    const float inv = 1.0f / s;

#pragma unroll
    for (int c = 0; c < 2; c++) {
        const int j0 = c * 1024 + tid * 4;
        if (j0 < kend) {
            __half2* dst = (__half2*)(ph + j0);
            dst[0] = __floats2half2_rn(v[c][0] * inv, v[c][1] * inv);
            dst[1] = __floats2half2_rn(v[c][2] * inv, v[c][3] * inv);
        }
    }
}

__global__ __launch_bounds__(128) void pv_kernel(float* __restrict__ out) {
    // LPT: biggest q-tiles (most k-iters) launch first
    int qt = NQT - 1 - blockIdx.y;
    int et = blockIdx.x, b = blockIdx.z;
    // causal: k range = (qt+1)*128 => kIters = (qt+1)*2 at BK=64
    gemm_fp16<0>(g_Ph + (size_t)b * SEQ * SEQ, g_Vth + (size_t)b * DIM * SEQ,
                 out + (size_t)b * SEQ * DIM, nullptr,
                 SEQ, SEQ, DIM, (qt + 1) * 2, qt * 128, et * 128, qt * 128);
}

// ---------------------------------------------------------------------------
extern "C" void kernel_launch(void* const* d_in, const int* in_sizes, int n_in,
                              void* d_out, int out_size) {
    int xi = 0;
    for (int i = 0; i < n_in; i++)
        if (in_sizes[i] == BATCH * SEQ * DIM) { xi = i; break; }
    const float* x = (const float*)d_in[xi];
    const float* w[3];
    int wi = 0;
    for (int i = 0; i < n_in && wi < 3; i++)
        if (i != xi) w[wi++] = (const float*)d_in[i];
    float* out = (float*)d_out;

    cudaFuncSetAttribute(proj_kernel,
                         cudaFuncAttributeMaxDynamicSharedMemorySize, SMEM_GEMM);
    cudaFuncSetAttribute(scores_kernel,
                         cudaFuncAttributeMaxDynamicSharedMemorySize, SMEM_GEMM);
    cudaFuncSetAttribute(pv_kernel,
                         cudaFuncAttributeMaxDynamicSharedMemorySize, SMEM_GEMM);

    cvt_kernel<<<dim3(512, 4), 256>>>((const float4*)x, (const float4*)w[0],
                                      (const float4*)w[1], (const float4*)w[2]);
    proj_kernel<<<dim3(8, 64, 3), 128, SMEM_GEMM>>>();
    scores_kernel<<<dim3(NTRI, 1, 4), 128, SMEM_GEMM>>>();
    softmax_kernel<<<BATCH * SEQ, 256>>>();
    pv_kernel<<<dim3(8, 16, 4), 128, SMEM_GEMM>>>(out);
}